// round 14
// baseline (speedup 1.0000x reference)
#include <cuda_runtime.h>
#include <cuda_bf16.h>
#include <float.h>

#define IMG_W   2048
#define IMG_H   2048
#define WM1     2047.0f
#define TPB     128
#define BUILD_TPB 256
#define MAXBLK  4096
#define SPLIT   4          // threads per point
#define G       5          // loads batched per group
#define QSCALE  65535.0f
#define QINV    (1.0f / 65535.0f)

// u16 quad table: tab[y*2048+x] = round(65535 * {img[y][x], img[y][x1], img[y1][x], img[y1][x1]})
__device__ ushort4 g_tab[IMG_W * IMG_H];         // 32 MB -> L2-resident with img
__device__ float g_partials[MAXBLK];
__device__ unsigned int g_count;                 // zero-init; wraps via atomicInc

__device__ __forceinline__ unsigned short quant(float v) {
    return (unsigned short)min(__float2uint_rn(v * QSCALE), 65535u);
}

__global__ void __launch_bounds__(BUILD_TPB)
build_tab_kernel(const float* __restrict__ img) {
    int tid = blockIdx.x * BUILD_TPB + threadIdx.x;
    int y  = tid >> 9;
    int xg = (tid & 511) << 2;
    int y1 = min(y + 1, IMG_H - 1);
    const float4* r0v = (const float4*)(img + y  * IMG_W);
    const float4* r1v = (const float4*)(img + y1 * IMG_W);
    float4 a = __ldg(&r0v[xg >> 2]);
    float4 c = __ldg(&r1v[xg >> 2]);
    int x4 = min(xg + 4, IMG_W - 1);
    float a4 = __ldg(img + y  * IMG_W + x4);
    float c4 = __ldg(img + y1 * IMG_W + x4);
    ushort4* dst = &g_tab[y * IMG_W + xg];
    dst[0] = make_ushort4(quant(a.x), quant(a.y), quant(c.x), quant(c.y));
    dst[1] = make_ushort4(quant(a.y), quant(a.z), quant(c.y), quant(c.z));
    dst[2] = make_ushort4(quant(a.z), quant(a.w), quant(c.z), quant(c.w));
    dst[3] = make_ushort4(quant(a.w), quant(a4),  quant(c.w), quant(c4));
}

// coords must be pre-clamped to [0, 2047]
__device__ __forceinline__ ushort4 quad_at(float x, float y) {
    int ix = (int)x;                 // F2I.TRUNC (x >= 0)
    int iy = (int)y;
    return __ldg(&g_tab[iy * IMG_W + ix]);   // IMAD
}

// interpolated value in u16 units (scale deferred to the end); lerp form
__device__ __forceinline__ float interp(ushort4 q, float x, float y) {
    float wx = x - truncf(x);
    float wy = y - truncf(y);
    float qa = (float)q.x, qb = (float)q.y, qc = (float)q.z, qd = (float)q.w;
    float top = fmaf(wx, qb - qa, qa);
    float bot = fmaf(wx, qd - qc, qc);
    return fmaf(wy, bot - top, top);
}

__global__ void __launch_bounds__(TPB)
contour_loss_kernel(const float* __restrict__ points,
                    const float* __restrict__ normals,
                    float* __restrict__ out,
                    int N, int nblocks, float inv_n) {
    int gtid = blockIdx.x * TPB + threadIdx.x;
    int pt  = gtid >> 2;        // point index
    int sub = gtid & 3;         // segment index within point
    int ptc = min(pt, N - 1);   // all lanes stay active (shuffle safety)
    bool valid = (pt < N);

    float px = fminf(fmaxf(__ldg(&points[2 * ptc]),     0.0f), WM1);
    float py = fminf(fmaxf(__ldg(&points[2 * ptc + 1]), 0.0f), WM1);
    float nx = __ldg(&normals[2 * ptc]);
    float ny = __ldg(&normals[2 * ptc + 1]);
    float dx = -ny, dy = nx;
    float inv = rsqrtf(dx * dx + dy * dy);
    dx *= inv; dy *= inv;

    float t_left  = (dx != 0.0f) ? (0.0f - px) / dx : -FLT_MAX;
    float t_right = (dx != 0.0f) ? (WM1  - px) / dx :  FLT_MAX;
    float t_top   = (dy != 0.0f) ? (0.0f - py) / dy : -FLT_MAX;
    float t_bot   = (dy != 0.0f) ? (WM1  - py) / dy :  FLT_MAX;
    float t_min = fmaxf(t_left,  t_top);
    float t_max = fminf(t_right, t_bot);

    float p1x = fmaf(t_min, dx, px), p1y = fmaf(t_min, dy, py);
    float p2x = fmaf(t_max, dx, px), p2y = fmaf(t_max, dy, py);
    // fold the 1/99 step into the direction once: coord(s) = fma(s, sv, p1)
    float svx = (p2x - p1x) * (1.0f / 99.0f);
    float svy = (p2y - p1y) * (1.0f / 99.0f);

    int s0 = sub * 25;          // this thread owns samples [s0, s0+24]
    float fs0 = (float)s0;      // exact (<= 75)

    // clamped sample coords; fs is the sample index as an exact float.
    // Clamps are load-bearing (inverted t-intervals put raw coords far
    // outside the image for ~half the points).
    #define CL(v)   fminf(fmaxf((v), 0.0f), WM1)
    #define SXF(fs) CL(fmaf((fs), svx, p1x))
    #define SYF(fs) CL(fmaf((fs), svy, p1y))

    // ref sample: only sub 0
    float ref_val = 0.0f;
    if (sub == 0) {
        ushort4 qr = quad_at(px, py);
        ref_val = interp(qr, px, py);
    }

    // prologue: first group's 5 loads in flight
    ushort4 qA[G], qB[G];
    #pragma unroll
    for (int j = 0; j < G; j++)
        qA[j] = quad_at(SXF(fs0 + (float)j), SYF(fs0 + (float)j));

    float v_prev = 0.0f, v_cur = 0.0f, cx = 0.0f, cy = 0.0f;
    float v_first = 0.0f, v_second = 0.0f, cfx = 0.0f, cfy = 0.0f;

    float best_dist = FLT_MAX;   // squared distance (argmin-equivalent)
    int   best_idx  = (sub == 0) ? 0x7FFFFFFE : 0x7FFFFFFF;
    float best_val  = 0.0f;

    // 5 groups x 5 samples, double-buffered; coords recomputed bit-identically
    // at consume (same expression, same exact-int fs) -> no stored coords.
    float fg_pre = fs0 + 5.0f;   // float base of next group's samples
    float fg_con = fs0;          // float base of current group's samples
    for (int g = 0; g < 5; g++) {               // rolled (R8/R12 lesson)
        if (g < 4) {
            #pragma unroll
            for (int j = 0; j < G; j++)
                qB[j] = quad_at(SXF(fg_pre + (float)j), SYF(fg_pre + (float)j));
        }
        int kbase = g * G;
        #pragma unroll
        for (int j = 0; j < G; j++) {
            int k = kbase + j;                   // local sample index 0..24
            float ax = SXF(fg_con + (float)j);
            float ay = SYF(fg_con + (float)j);
            float vn = interp(qA[j], ax, ay);
            if (k == 0) {
                v_first = vn; cfx = ax; cfy = ay;
                v_cur = vn;
            } else {
                if (k == 1) v_second = vn;
                if (k >= 2 && v_cur < v_prev && v_cur < vn) {
                    // interior window center k-1 (global s0+k-1); coords (cx,cy)
                    float ddx = cx - px, ddy = cy - py;
                    float d2 = fmaf(ddx, ddx, ddy * ddy);
                    if (d2 < best_dist) {        // ascending + strict < = first min
                        best_dist = d2;
                        best_idx  = s0 + k - 1;
                        best_val  = v_cur;
                    }
                }
                v_prev = v_cur;
                v_cur  = vn;
            }
            cx = ax; cy = ay;
        }
        #pragma unroll
        for (int j = 0; j < G; j++)
            qA[j] = qB[j];
        fg_pre += 5.0f;          // exact small-int floats
        fg_con += 5.0f;
    }
    #undef CL
    #undef SXF
    #undef SYF

    // boundary values from neighbor subs (same warp, adjacent lanes)
    float nb_last  = __shfl_up_sync(0xFFFFFFFFu, v_cur, 1);    // prev sub's v[24]
    float nb_first = __shfl_down_sync(0xFFFFFFFFu, v_first, 1);// next sub's v[0]

    // left-boundary window: center s0 (sub>0): (nb_last, v_first, v_second)
    if (sub > 0 && v_first < nb_last && v_first < v_second) {
        float ddx = cfx - px, ddy = cfy - py;
        float d2 = fmaf(ddx, ddx, ddy * ddy);
        if (d2 < best_dist || (d2 == best_dist && s0 < best_idx)) {
            best_dist = d2; best_idx = s0; best_val = v_first;
        }
    }
    // right-boundary window: center s0+24 (sub<3): (v_prev, v_cur, nb_first)
    if (sub < 3 && v_cur < v_prev && v_cur < nb_first) {
        float ddx = cx - px, ddy = cy - py;
        float d2 = fmaf(ddx, ddx, ddy * ddy);
        if (d2 < best_dist || (d2 == best_dist && (s0 + 24) < best_idx)) {
            best_dist = d2; best_idx = s0 + 24; best_val = v_cur;
        }
    }
    // all-inf default: argmin -> 0 -> vals[1] = global sample 1 = sub0's v_second
    if (sub == 0 && best_idx == 0x7FFFFFFE) best_val = v_second;

    // combine across the 4 sub-threads (lexicographic on (dist2, idx))
    #pragma unroll
    for (int m = 1; m <= 2; m <<= 1) {
        float od = __shfl_xor_sync(0xFFFFFFFFu, best_dist, m);
        int   oi = __shfl_xor_sync(0xFFFFFFFFu, best_idx,  m);
        float ov = __shfl_xor_sync(0xFFFFFFFFu, best_val,  m);
        if (od < best_dist || (od == best_dist && oi < best_idx)) {
            best_dist = od; best_idx = oi; best_val = ov;
        }
    }

    float sq = 0.0f;
    if (valid && sub == 0) {
        float diff = (best_val - ref_val) * QINV;   // scale once
        sq = diff * diff;
    }

    // ── block reduction (deterministic) ──
    __shared__ float smem[TPB / 32];
    __shared__ bool s_last;
    float v = sq;
    #pragma unroll
    for (int off = 16; off > 0; off >>= 1)
        v += __shfl_down_sync(0xFFFFFFFFu, v, off);
    int lane = threadIdx.x & 31;
    int wid  = threadIdx.x >> 5;
    if (lane == 0) smem[wid] = v;
    __syncthreads();
    if (wid == 0) {
        v = (lane < TPB / 32) ? smem[lane] : 0.0f;
        #pragma unroll
        for (int off = 2; off > 0; off >>= 1)
            v += __shfl_down_sync(0xFFFFFFFFu, v, off);
        if (lane == 0) {
            g_partials[blockIdx.x] = v;
            __threadfence();
            unsigned int t = atomicInc(&g_count, (unsigned int)(nblocks - 1));
            s_last = (t == (unsigned int)(nblocks - 1));
        }
    }
    __syncthreads();

    if (s_last) {
        float acc = 0.0f;
        for (int k = threadIdx.x; k < nblocks; k += TPB)
            acc += g_partials[k];
        #pragma unroll
        for (int off = 16; off > 0; off >>= 1)
            acc += __shfl_down_sync(0xFFFFFFFFu, acc, off);
        if (lane == 0) smem[wid] = acc;
        __syncthreads();
        if (wid == 0) {
            acc = (lane < TPB / 32) ? smem[lane] : 0.0f;
            #pragma unroll
            for (int off = 2; off > 0; off >>= 1)
                acc += __shfl_down_sync(0xFFFFFFFFu, acc, off);
            if (lane == 0) out[0] = acc * inv_n;
        }
    }
}

extern "C" void kernel_launch(void* const* d_in, const int* in_sizes, int n_in,
                              void* d_out, int out_size) {
    const float* img     = (const float*)d_in[0];
    const float* points  = (const float*)d_in[1];
    const float* normals = (const float*)d_in[2];
    float* out = (float*)d_out;

    int N = in_sizes[1] / 2;
    int total = N * SPLIT;
    int blocks = (total + TPB - 1) / TPB;

    build_tab_kernel<<<(IMG_W * (IMG_W / 4)) / BUILD_TPB, BUILD_TPB>>>(img);
    contour_loss_kernel<<<blocks, TPB>>>(points, normals, out, N, blocks,
                                         1.0f / (float)N);
}

// round 15
// speedup vs baseline: 1.2307x; 1.2307x over previous
#include <cuda_runtime.h>
#include <cuda_bf16.h>
#include <float.h>

#define IMG_W   2048
#define IMG_H   2048
#define WM1     2047.0f
#define TPB     128
#define BUILD_TPB 256
#define MAXBLK  4096
#define SPLIT   4          // threads per point
#define G       5          // loads batched per group
#define QSCALE  65535.0f
#define QINV    (1.0f / 65535.0f)

// u16 quad table: tab[y*2048+x] = round(65535 * {img[y][x], img[y][x1], img[y1][x], img[y1][x1]})
__device__ ushort4 g_tab[IMG_W * IMG_H];         // 32 MB -> L2-resident with img
__device__ float g_partials[MAXBLK];
__device__ unsigned int g_count;                 // zero-init; wraps via atomicInc

__device__ __forceinline__ unsigned int quant_u(float v) {
    return min(__float2uint_rn(v * QSCALE), 65535u);
}

// Coalesced build: 1 thread per 2 pixels (x even). Per warp: 2 coalesced
// float2 loads per row + shfl for the x+2 neighbor, one uint4 (2 quads) store.
__global__ void __launch_bounds__(BUILD_TPB)
build_tab_kernel(const float* __restrict__ img) {
    int tid  = blockIdx.x * BUILD_TPB + threadIdx.x;   // 2048*1024 threads
    int y    = tid >> 10;                              // row
    int j    = tid & 1023;                             // float2 index in row
    int x    = j << 1;                                 // even pixel
    int y1   = min(y + 1, IMG_H - 1);
    int lane = threadIdx.x & 31;

    const float2* r0 = (const float2*)(img + y  * IMG_W);
    const float2* r1 = (const float2*)(img + y1 * IMG_W);
    float2 a = __ldg(&r0[j]);          // row0[x], row0[x+1]
    float2 c = __ldg(&r1[j]);          // row1[x], row1[x+1]

    // row[x+2] from the next lane (rows are warp-aligned: 1024 = 32*32)
    float a2 = __shfl_down_sync(0xFFFFFFFFu, a.x, 1);
    float c2 = __shfl_down_sync(0xFFFFFFFFu, c.x, 1);
    if (lane == 31) {                  // warp edge (includes row edge j=1023)
        int xn = min(x + 2, IMG_W - 1);
        a2 = __ldg(img + y  * IMG_W + xn);
        c2 = __ldg(img + y1 * IMG_W + xn);
    }

    unsigned int qa0 = quant_u(a.x), qa1 = quant_u(a.y), qa2 = quant_u(a2);
    unsigned int qc0 = quant_u(c.x), qc1 = quant_u(c.y), qc2 = quant_u(c2);

    uint4 v;
    v.x = qa0 | (qa1 << 16);           // pixel x:   row0 pair
    v.y = qc0 | (qc1 << 16);           //            row1 pair
    v.z = qa1 | (qa2 << 16);           // pixel x+1: row0 pair
    v.w = qc1 | (qc2 << 16);           //            row1 pair
    *reinterpret_cast<uint4*>(&g_tab[y * IMG_W + x]) = v;   // 16B aligned
}

// coords must be pre-clamped to [0, 2047]
__device__ __forceinline__ ushort4 quad_at(float x, float y) {
    int ix = (int)x;                 // F2I.TRUNC (x >= 0)
    int iy = (int)y;
    return __ldg(&g_tab[iy * IMG_W + ix]);   // IMAD
}

// interpolated value in u16 units (scale deferred to the end); lerp form
__device__ __forceinline__ float interp(ushort4 q, float x, float y) {
    float wx = x - truncf(x);
    float wy = y - truncf(y);
    float qa = (float)q.x, qb = (float)q.y, qc = (float)q.z, qd = (float)q.w;
    float top = fmaf(wx, qb - qa, qa);
    float bot = fmaf(wx, qd - qc, qc);
    return fmaf(wy, bot - top, top);
}

__global__ void __launch_bounds__(TPB)
contour_loss_kernel(const float* __restrict__ points,
                    const float* __restrict__ normals,
                    float* __restrict__ out,
                    int N, int nblocks, float inv_n) {
    int gtid = blockIdx.x * TPB + threadIdx.x;
    int pt  = gtid >> 2;        // point index
    int sub = gtid & 3;         // segment index within point
    int ptc = min(pt, N - 1);   // all lanes stay active (shuffle safety)
    bool valid = (pt < N);

    float px = fminf(fmaxf(__ldg(&points[2 * ptc]),     0.0f), WM1);
    float py = fminf(fmaxf(__ldg(&points[2 * ptc + 1]), 0.0f), WM1);
    float nx = __ldg(&normals[2 * ptc]);
    float ny = __ldg(&normals[2 * ptc + 1]);
    float dx = -ny, dy = nx;
    float inv = rsqrtf(dx * dx + dy * dy);
    dx *= inv; dy *= inv;

    float t_left  = (dx != 0.0f) ? (0.0f - px) / dx : -FLT_MAX;
    float t_right = (dx != 0.0f) ? (WM1  - px) / dx :  FLT_MAX;
    float t_top   = (dy != 0.0f) ? (0.0f - py) / dy : -FLT_MAX;
    float t_bot   = (dy != 0.0f) ? (WM1  - py) / dy :  FLT_MAX;
    float t_min = fmaxf(t_left,  t_top);
    float t_max = fminf(t_right, t_bot);

    float p1x = fmaf(t_min, dx, px), p1y = fmaf(t_min, dy, py);
    float p2x = fmaf(t_max, dx, px), p2y = fmaf(t_max, dy, py);
    // fold the 1/99 step into the direction once: coord(s) = fma(s, sv, p1)
    float svx = (p2x - p1x) * (1.0f / 99.0f);
    float svy = (p2y - p1y) * (1.0f / 99.0f);

    int s0 = sub * 25;          // this thread owns samples [s0, s0+24]
    float fs0 = (float)s0;      // exact (<= 75)

    // clamped sample coords; fs is the sample index as an exact float.
    // Clamps are load-bearing (inverted t-intervals put raw coords far
    // outside the image for ~half the points).
    #define CL(v)   fminf(fmaxf((v), 0.0f), WM1)
    #define SXF(fs) CL(fmaf((fs), svx, p1x))
    #define SYF(fs) CL(fmaf((fs), svy, p1y))

    // ref sample: only sub 0
    float ref_val = 0.0f;
    if (sub == 0) {
        ushort4 qr = quad_at(px, py);
        ref_val = interp(qr, px, py);
    }

    // prologue: first group's 5 loads in flight
    ushort4 qA[G], qB[G];
    #pragma unroll
    for (int j = 0; j < G; j++)
        qA[j] = quad_at(SXF(fs0 + (float)j), SYF(fs0 + (float)j));

    float v_prev = 0.0f, v_cur = 0.0f, cx = 0.0f, cy = 0.0f;
    float v_first = 0.0f, v_second = 0.0f, cfx = 0.0f, cfy = 0.0f;

    float best_dist = FLT_MAX;   // squared distance (argmin-equivalent)
    int   best_idx  = (sub == 0) ? 0x7FFFFFFE : 0x7FFFFFFF;
    float best_val  = 0.0f;

    // 5 groups x 5 samples, double-buffered; coords recomputed bit-identically
    // at consume (same expression, same exact-int fs) -> no stored coords.
    float fg_pre = fs0 + 5.0f;   // float base of next group's samples
    float fg_con = fs0;          // float base of current group's samples
    for (int g = 0; g < 5; g++) {               // rolled (R8/R12 lesson)
        if (g < 4) {
            #pragma unroll
            for (int j = 0; j < G; j++)
                qB[j] = quad_at(SXF(fg_pre + (float)j), SYF(fg_pre + (float)j));
        }
        int kbase = g * G;
        #pragma unroll
        for (int j = 0; j < G; j++) {
            int k = kbase + j;                   // local sample index 0..24
            float ax = SXF(fg_con + (float)j);
            float ay = SYF(fg_con + (float)j);
            float vn = interp(qA[j], ax, ay);
            if (k == 0) {
                v_first = vn; cfx = ax; cfy = ay;
                v_cur = vn;
            } else {
                if (k == 1) v_second = vn;
                if (k >= 2 && v_cur < v_prev && v_cur < vn) {
                    // interior window center k-1 (global s0+k-1); coords (cx,cy)
                    float ddx = cx - px, ddy = cy - py;
                    float d2 = fmaf(ddx, ddx, ddy * ddy);
                    if (d2 < best_dist) {        // ascending + strict < = first min
                        best_dist = d2;
                        best_idx  = s0 + k - 1;
                        best_val  = v_cur;
                    }
                }
                v_prev = v_cur;
                v_cur  = vn;
            }
            cx = ax; cy = ay;
        }
        #pragma unroll
        for (int j = 0; j < G; j++)
            qA[j] = qB[j];
        fg_pre += 5.0f;          // exact small-int floats
        fg_con += 5.0f;
    }
    #undef CL
    #undef SXF
    #undef SYF

    // boundary values from neighbor subs (same warp, adjacent lanes)
    float nb_last  = __shfl_up_sync(0xFFFFFFFFu, v_cur, 1);    // prev sub's v[24]
    float nb_first = __shfl_down_sync(0xFFFFFFFFu, v_first, 1);// next sub's v[0]

    // left-boundary window: center s0 (sub>0): (nb_last, v_first, v_second)
    if (sub > 0 && v_first < nb_last && v_first < v_second) {
        float ddx = cfx - px, ddy = cfy - py;
        float d2 = fmaf(ddx, ddx, ddy * ddy);
        if (d2 < best_dist || (d2 == best_dist && s0 < best_idx)) {
            best_dist = d2; best_idx = s0; best_val = v_first;
        }
    }
    // right-boundary window: center s0+24 (sub<3): (v_prev, v_cur, nb_first)
    if (sub < 3 && v_cur < v_prev && v_cur < nb_first) {
        float ddx = cx - px, ddy = cy - py;
        float d2 = fmaf(ddx, ddx, ddy * ddy);
        if (d2 < best_dist || (d2 == best_dist && (s0 + 24) < best_idx)) {
            best_dist = d2; best_idx = s0 + 24; best_val = v_cur;
        }
    }
    // all-inf default: argmin -> 0 -> vals[1] = global sample 1 = sub0's v_second
    if (sub == 0 && best_idx == 0x7FFFFFFE) best_val = v_second;

    // combine across the 4 sub-threads (lexicographic on (dist2, idx))
    #pragma unroll
    for (int m = 1; m <= 2; m <<= 1) {
        float od = __shfl_xor_sync(0xFFFFFFFFu, best_dist, m);
        int   oi = __shfl_xor_sync(0xFFFFFFFFu, best_idx,  m);
        float ov = __shfl_xor_sync(0xFFFFFFFFu, best_val,  m);
        if (od < best_dist || (od == best_dist && oi < best_idx)) {
            best_dist = od; best_idx = oi; best_val = ov;
        }
    }

    float sq = 0.0f;
    if (valid && sub == 0) {
        float diff = (best_val - ref_val) * QINV;   // scale once
        sq = diff * diff;
    }

    // ── block reduction (deterministic) ──
    __shared__ float smem[TPB / 32];
    __shared__ bool s_last;
    float v = sq;
    #pragma unroll
    for (int off = 16; off > 0; off >>= 1)
        v += __shfl_down_sync(0xFFFFFFFFu, v, off);
    int lane = threadIdx.x & 31;
    int wid  = threadIdx.x >> 5;
    if (lane == 0) smem[wid] = v;
    __syncthreads();
    if (wid == 0) {
        v = (lane < TPB / 32) ? smem[lane] : 0.0f;
        #pragma unroll
        for (int off = 2; off > 0; off >>= 1)
            v += __shfl_down_sync(0xFFFFFFFFu, v, off);
        if (lane == 0) {
            g_partials[blockIdx.x] = v;
            __threadfence();
            unsigned int t = atomicInc(&g_count, (unsigned int)(nblocks - 1));
            s_last = (t == (unsigned int)(nblocks - 1));
        }
    }
    __syncthreads();

    if (s_last) {
        float acc = 0.0f;
        for (int k = threadIdx.x; k < nblocks; k += TPB)
            acc += g_partials[k];
        #pragma unroll
        for (int off = 16; off > 0; off >>= 1)
            acc += __shfl_down_sync(0xFFFFFFFFu, acc, off);
        if (lane == 0) smem[wid] = acc;
        __syncthreads();
        if (wid == 0) {
            acc = (lane < TPB / 32) ? smem[lane] : 0.0f;
            #pragma unroll
            for (int off = 2; off > 0; off >>= 1)
                acc += __shfl_down_sync(0xFFFFFFFFu, acc, off);
            if (lane == 0) out[0] = acc * inv_n;
        }
    }
}

extern "C" void kernel_launch(void* const* d_in, const int* in_sizes, int n_in,
                              void* d_out, int out_size) {
    const float* img     = (const float*)d_in[0];
    const float* points  = (const float*)d_in[1];
    const float* normals = (const float*)d_in[2];
    float* out = (float*)d_out;

    int N = in_sizes[1] / 2;
    int total = N * SPLIT;
    int blocks = (total + TPB - 1) / TPB;

    // 1 thread per 2 pixels: 2048 rows * 1024 = 2,097,152 threads
    build_tab_kernel<<<(IMG_W * (IMG_W / 2)) / BUILD_TPB, BUILD_TPB>>>(img);
    contour_loss_kernel<<<blocks, TPB>>>(points, normals, out, N, blocks,
                                         1.0f / (float)N);
}

// round 16
// speedup vs baseline: 1.2411x; 1.0085x over previous
#include <cuda_runtime.h>
#include <cuda_bf16.h>
#include <float.h>

#define IMG_W   2048
#define IMG_H   2048
#define WM1     2047.0f
#define TPB     128
#define BUILD_TPB 256
#define MAXBLK  4096
#define SPLIT   4          // threads per point
#define G       5          // loads batched per group
#define ROWS_PT 4          // output rows per build thread
#define QSCALE  65535.0f
#define QINV    (1.0f / 65535.0f)

// u16 quad table: tab[y*2048+x] = round(65535 * {img[y][x], img[y][x1], img[y1][x], img[y1][x1]})
__device__ ushort4 g_tab[IMG_W * IMG_H];         // 32 MB -> L2-resident with img
__device__ float g_partials[MAXBLK];
__device__ unsigned int g_count;                 // zero-init; wraps via atomicInc

__device__ __forceinline__ unsigned int quant_u(float v) {
    return min(__float2uint_rn(v * QSCALE), 65535u);
}

// Coalesced build with row reuse: 1 thread per 2 columns x 4 output rows.
// Loads 5 row-segments (float2, coalesced), each interior row reused for two
// output rows -> read amplification 1.25x instead of 2x. Shuffle for x+2.
__global__ void __launch_bounds__(BUILD_TPB)
build_tab_kernel(const float* __restrict__ img) {
    int tid  = blockIdx.x * BUILD_TPB + threadIdx.x;   // 512*1024 threads
    int y0   = (tid >> 10) * ROWS_PT;                  // first output row
    int j    = tid & 1023;                             // float2 index in row
    int x    = j << 1;                                 // even pixel
    int lane = threadIdx.x & 31;

    float2 a[ROWS_PT + 1];
    float  a2[ROWS_PT + 1];
    #pragma unroll
    for (int r = 0; r <= ROWS_PT; r++) {
        int yr = min(y0 + r, IMG_H - 1);               // only r=4 can clamp
        a[r] = __ldg((const float2*)(img + yr * IMG_W) + j);
    }
    #pragma unroll
    for (int r = 0; r <= ROWS_PT; r++)
        a2[r] = __shfl_down_sync(0xFFFFFFFFu, a[r].x, 1);
    if (lane == 31) {                  // warp edge (includes row edge j=1023)
        int xn = min(x + 2, IMG_W - 1);
        #pragma unroll
        for (int r = 0; r <= ROWS_PT; r++) {
            int yr = min(y0 + r, IMG_H - 1);
            a2[r] = __ldg(img + yr * IMG_W + xn);
        }
    }

    unsigned int q0[ROWS_PT + 1], q1[ROWS_PT + 1], q2[ROWS_PT + 1];
    #pragma unroll
    for (int r = 0; r <= ROWS_PT; r++) {
        q0[r] = quant_u(a[r].x);
        q1[r] = quant_u(a[r].y);
        q2[r] = quant_u(a2[r]);
    }

    #pragma unroll
    for (int r = 0; r < ROWS_PT; r++) {
        uint4 v;
        v.x = q0[r]     | (q1[r]     << 16);   // pixel x:   row r pair
        v.y = q0[r + 1] | (q1[r + 1] << 16);   //            row r+1 pair
        v.z = q1[r]     | (q2[r]     << 16);   // pixel x+1: row r pair
        v.w = q1[r + 1] | (q2[r + 1] << 16);   //            row r+1 pair
        *reinterpret_cast<uint4*>(&g_tab[(y0 + r) * IMG_W + x]) = v;
    }
}

// coords must be pre-clamped to [0, 2047]
__device__ __forceinline__ ushort4 quad_at(float x, float y) {
    int ix = (int)x;                 // F2I.TRUNC (x >= 0)
    int iy = (int)y;
    return __ldg(&g_tab[iy * IMG_W + ix]);   // IMAD
}

// interpolated value in u16 units (scale deferred to the end); lerp form
__device__ __forceinline__ float interp(ushort4 q, float x, float y) {
    float wx = x - truncf(x);
    float wy = y - truncf(y);
    float qa = (float)q.x, qb = (float)q.y, qc = (float)q.z, qd = (float)q.w;
    float top = fmaf(wx, qb - qa, qa);
    float bot = fmaf(wx, qd - qc, qc);
    return fmaf(wy, bot - top, top);
}

__global__ void __launch_bounds__(TPB)
contour_loss_kernel(const float* __restrict__ points,
                    const float* __restrict__ normals,
                    float* __restrict__ out,
                    int N, int nblocks, float inv_n) {
    int gtid = blockIdx.x * TPB + threadIdx.x;
    int pt  = gtid >> 2;        // point index
    int sub = gtid & 3;         // segment index within point
    int ptc = min(pt, N - 1);   // all lanes stay active (shuffle safety)
    bool valid = (pt < N);

    float px = fminf(fmaxf(__ldg(&points[2 * ptc]),     0.0f), WM1);
    float py = fminf(fmaxf(__ldg(&points[2 * ptc + 1]), 0.0f), WM1);
    float nx = __ldg(&normals[2 * ptc]);
    float ny = __ldg(&normals[2 * ptc + 1]);
    float dx = -ny, dy = nx;
    float inv = rsqrtf(dx * dx + dy * dy);
    dx *= inv; dy *= inv;

    float t_left  = (dx != 0.0f) ? (0.0f - px) / dx : -FLT_MAX;
    float t_right = (dx != 0.0f) ? (WM1  - px) / dx :  FLT_MAX;
    float t_top   = (dy != 0.0f) ? (0.0f - py) / dy : -FLT_MAX;
    float t_bot   = (dy != 0.0f) ? (WM1  - py) / dy :  FLT_MAX;
    float t_min = fmaxf(t_left,  t_top);
    float t_max = fminf(t_right, t_bot);

    float p1x = fmaf(t_min, dx, px), p1y = fmaf(t_min, dy, py);
    float p2x = fmaf(t_max, dx, px), p2y = fmaf(t_max, dy, py);
    // fold the 1/99 step into the direction once: coord(s) = fma(s, sv, p1)
    float svx = (p2x - p1x) * (1.0f / 99.0f);
    float svy = (p2y - p1y) * (1.0f / 99.0f);

    int s0 = sub * 25;          // this thread owns samples [s0, s0+24]
    float fs0 = (float)s0;      // exact (<= 75)

    // clamped sample coords; fs is the sample index as an exact float.
    // Clamps are load-bearing (inverted t-intervals put raw coords far
    // outside the image for ~half the points).
    #define CL(v)   fminf(fmaxf((v), 0.0f), WM1)
    #define SXF(fs) CL(fmaf((fs), svx, p1x))
    #define SYF(fs) CL(fmaf((fs), svy, p1y))

    // ref sample: only sub 0
    float ref_val = 0.0f;
    if (sub == 0) {
        ushort4 qr = quad_at(px, py);
        ref_val = interp(qr, px, py);
    }

    // prologue: first group's 5 loads in flight
    ushort4 qA[G], qB[G];
    #pragma unroll
    for (int j = 0; j < G; j++)
        qA[j] = quad_at(SXF(fs0 + (float)j), SYF(fs0 + (float)j));

    float v_prev = 0.0f, v_cur = 0.0f, cx = 0.0f, cy = 0.0f;
    float v_first = 0.0f, v_second = 0.0f, cfx = 0.0f, cfy = 0.0f;

    float best_dist = FLT_MAX;   // squared distance (argmin-equivalent)
    int   best_idx  = (sub == 0) ? 0x7FFFFFFE : 0x7FFFFFFF;
    float best_val  = 0.0f;

    // 5 groups x 5 samples, double-buffered; coords recomputed bit-identically
    // at consume (same expression, same exact-int fs) -> no stored coords.
    float fg_pre = fs0 + 5.0f;   // float base of next group's samples
    float fg_con = fs0;          // float base of current group's samples
    for (int g = 0; g < 5; g++) {               // rolled (R8/R12 lesson)
        if (g < 4) {
            #pragma unroll
            for (int j = 0; j < G; j++)
                qB[j] = quad_at(SXF(fg_pre + (float)j), SYF(fg_pre + (float)j));
        }
        int kbase = g * G;
        #pragma unroll
        for (int j = 0; j < G; j++) {
            int k = kbase + j;                   // local sample index 0..24
            float ax = SXF(fg_con + (float)j);
            float ay = SYF(fg_con + (float)j);
            float vn = interp(qA[j], ax, ay);
            if (k == 0) {
                v_first = vn; cfx = ax; cfy = ay;
                v_cur = vn;
            } else {
                if (k == 1) v_second = vn;
                if (k >= 2 && v_cur < v_prev && v_cur < vn) {
                    // interior window center k-1 (global s0+k-1); coords (cx,cy)
                    float ddx = cx - px, ddy = cy - py;
                    float d2 = fmaf(ddx, ddx, ddy * ddy);
                    if (d2 < best_dist) {        // ascending + strict < = first min
                        best_dist = d2;
                        best_idx  = s0 + k - 1;
                        best_val  = v_cur;
                    }
                }
                v_prev = v_cur;
                v_cur  = vn;
            }
            cx = ax; cy = ay;
        }
        #pragma unroll
        for (int j = 0; j < G; j++)
            qA[j] = qB[j];
        fg_pre += 5.0f;          // exact small-int floats
        fg_con += 5.0f;
    }
    #undef CL
    #undef SXF
    #undef SYF

    // boundary values from neighbor subs (same warp, adjacent lanes)
    float nb_last  = __shfl_up_sync(0xFFFFFFFFu, v_cur, 1);    // prev sub's v[24]
    float nb_first = __shfl_down_sync(0xFFFFFFFFu, v_first, 1);// next sub's v[0]

    // left-boundary window: center s0 (sub>0): (nb_last, v_first, v_second)
    if (sub > 0 && v_first < nb_last && v_first < v_second) {
        float ddx = cfx - px, ddy = cfy - py;
        float d2 = fmaf(ddx, ddx, ddy * ddy);
        if (d2 < best_dist || (d2 == best_dist && s0 < best_idx)) {
            best_dist = d2; best_idx = s0; best_val = v_first;
        }
    }
    // right-boundary window: center s0+24 (sub<3): (v_prev, v_cur, nb_first)
    if (sub < 3 && v_cur < v_prev && v_cur < nb_first) {
        float ddx = cx - px, ddy = cy - py;
        float d2 = fmaf(ddx, ddx, ddy * ddy);
        if (d2 < best_dist || (d2 == best_dist && (s0 + 24) < best_idx)) {
            best_dist = d2; best_idx = s0 + 24; best_val = v_cur;
        }
    }
    // all-inf default: argmin -> 0 -> vals[1] = global sample 1 = sub0's v_second
    if (sub == 0 && best_idx == 0x7FFFFFFE) best_val = v_second;

    // combine across the 4 sub-threads (lexicographic on (dist2, idx))
    #pragma unroll
    for (int m = 1; m <= 2; m <<= 1) {
        float od = __shfl_xor_sync(0xFFFFFFFFu, best_dist, m);
        int   oi = __shfl_xor_sync(0xFFFFFFFFu, best_idx,  m);
        float ov = __shfl_xor_sync(0xFFFFFFFFu, best_val,  m);
        if (od < best_dist || (od == best_dist && oi < best_idx)) {
            best_dist = od; best_idx = oi; best_val = ov;
        }
    }

    float sq = 0.0f;
    if (valid && sub == 0) {
        float diff = (best_val - ref_val) * QINV;   // scale once
        sq = diff * diff;
    }

    // ── block reduction (deterministic) ──
    __shared__ float smem[TPB / 32];
    __shared__ bool s_last;
    float v = sq;
    #pragma unroll
    for (int off = 16; off > 0; off >>= 1)
        v += __shfl_down_sync(0xFFFFFFFFu, v, off);
    int lane = threadIdx.x & 31;
    int wid  = threadIdx.x >> 5;
    if (lane == 0) smem[wid] = v;
    __syncthreads();
    if (wid == 0) {
        v = (lane < TPB / 32) ? smem[lane] : 0.0f;
        #pragma unroll
        for (int off = 2; off > 0; off >>= 1)
            v += __shfl_down_sync(0xFFFFFFFFu, v, off);
        if (lane == 0) {
            g_partials[blockIdx.x] = v;
            __threadfence();
            unsigned int t = atomicInc(&g_count, (unsigned int)(nblocks - 1));
            s_last = (t == (unsigned int)(nblocks - 1));
        }
    }
    __syncthreads();

    if (s_last) {
        float acc = 0.0f;
        for (int k = threadIdx.x; k < nblocks; k += TPB)
            acc += g_partials[k];
        #pragma unroll
        for (int off = 16; off > 0; off >>= 1)
            acc += __shfl_down_sync(0xFFFFFFFFu, acc, off);
        if (lane == 0) smem[wid] = acc;
        __syncthreads();
        if (wid == 0) {
            acc = (lane < TPB / 32) ? smem[lane] : 0.0f;
            #pragma unroll
            for (int off = 2; off > 0; off >>= 1)
                acc += __shfl_down_sync(0xFFFFFFFFu, acc, off);
            if (lane == 0) out[0] = acc * inv_n;
        }
    }
}

extern "C" void kernel_launch(void* const* d_in, const int* in_sizes, int n_in,
                              void* d_out, int out_size) {
    const float* img     = (const float*)d_in[0];
    const float* points  = (const float*)d_in[1];
    const float* normals = (const float*)d_in[2];
    float* out = (float*)d_out;

    int N = in_sizes[1] / 2;
    int total = N * SPLIT;
    int blocks = (total + TPB - 1) / TPB;

    // 1 thread per 2 cols x 4 rows: (2048/4) * 1024 = 524,288 threads
    build_tab_kernel<<<((IMG_H / ROWS_PT) * (IMG_W / 2)) / BUILD_TPB, BUILD_TPB>>>(img);
    contour_loss_kernel<<<blocks, TPB>>>(points, normals, out, N, blocks,
                                         1.0f / (float)N);
}

// round 17
// speedup vs baseline: 1.2718x; 1.0247x over previous
#include <cuda_runtime.h>
#include <cuda_bf16.h>
#include <float.h>

#define IMG_W   2048
#define IMG_H   2048
#define WM1     2047.0f
#define TPB     128
#define BUILD_TPB 256
#define MAXBLK  4096
#define SPLIT   4          // threads per point
#define G       5          // loads batched per group
#define ROWS_PT 4          // output rows per build thread
#define QSCALE  65535.0f
#define QINV    (1.0f / 65535.0f)

// u16 quad table: tab[y*2048+x] = round(65535 * {img[y][x], img[y][x1], img[y1][x], img[y1][x1]})
__device__ ushort4 g_tab[IMG_W * IMG_H];         // 32 MB -> L2-resident with img
__device__ float g_partials[MAXBLK];
__device__ unsigned int g_count;                 // zero-init; wraps via atomicInc

__device__ __forceinline__ unsigned int quant_u(float v) {
    return min(__float2uint_rn(v * QSCALE), 65535u);
}

// Coalesced build with row reuse: 1 thread per 2 columns x 4 output rows.
__global__ void __launch_bounds__(BUILD_TPB)
build_tab_kernel(const float* __restrict__ img) {
    int tid  = blockIdx.x * BUILD_TPB + threadIdx.x;   // 512*1024 threads
    int y0   = (tid >> 10) * ROWS_PT;                  // first output row
    int j    = tid & 1023;                             // float2 index in row
    int x    = j << 1;                                 // even pixel
    int lane = threadIdx.x & 31;

    float2 a[ROWS_PT + 1];
    float  a2[ROWS_PT + 1];
    #pragma unroll
    for (int r = 0; r <= ROWS_PT; r++) {
        int yr = min(y0 + r, IMG_H - 1);               // only r=4 can clamp
        a[r] = __ldg((const float2*)(img + yr * IMG_W) + j);
    }
    #pragma unroll
    for (int r = 0; r <= ROWS_PT; r++)
        a2[r] = __shfl_down_sync(0xFFFFFFFFu, a[r].x, 1);
    if (lane == 31) {                  // warp edge (includes row edge j=1023)
        int xn = min(x + 2, IMG_W - 1);
        #pragma unroll
        for (int r = 0; r <= ROWS_PT; r++) {
            int yr = min(y0 + r, IMG_H - 1);
            a2[r] = __ldg(img + yr * IMG_W + xn);
        }
    }

    unsigned int q0[ROWS_PT + 1], q1[ROWS_PT + 1], q2[ROWS_PT + 1];
    #pragma unroll
    for (int r = 0; r <= ROWS_PT; r++) {
        q0[r] = quant_u(a[r].x);
        q1[r] = quant_u(a[r].y);
        q2[r] = quant_u(a2[r]);
    }

    #pragma unroll
    for (int r = 0; r < ROWS_PT; r++) {
        uint4 v;
        v.x = q0[r]     | (q1[r]     << 16);   // pixel x:   row r pair
        v.y = q0[r + 1] | (q1[r + 1] << 16);   //            row r+1 pair
        v.z = q1[r]     | (q2[r]     << 16);   // pixel x+1: row r pair
        v.w = q1[r + 1] | (q2[r + 1] << 16);   //            row r+1 pair
        *reinterpret_cast<uint4*>(&g_tab[(y0 + r) * IMG_W + x]) = v;
    }

    // PDL: allow the dependent kernel's preamble to launch; its
    // cudaGridDependencySynchronize() still waits for our full completion.
    cudaTriggerProgrammaticLaunchCompletion();
}

// coords must be pre-clamped to [0, 2047]
__device__ __forceinline__ ushort4 quad_at(float x, float y) {
    int ix = (int)x;                 // F2I.TRUNC (x >= 0)
    int iy = (int)y;
    return __ldg(&g_tab[iy * IMG_W + ix]);   // IMAD
}

// interpolated value in u16 units (scale deferred to the end); lerp form
__device__ __forceinline__ float interp(ushort4 q, float x, float y) {
    float wx = x - truncf(x);
    float wy = y - truncf(y);
    float qa = (float)q.x, qb = (float)q.y, qc = (float)q.z, qd = (float)q.w;
    float top = fmaf(wx, qb - qa, qa);
    float bot = fmaf(wx, qd - qc, qc);
    return fmaf(wy, bot - top, top);
}

__global__ void __launch_bounds__(TPB)
contour_loss_kernel(const float* __restrict__ points,
                    const float* __restrict__ normals,
                    float* __restrict__ out,
                    int N, int nblocks, float inv_n) {
    int gtid = blockIdx.x * TPB + threadIdx.x;
    int pt  = gtid >> 2;        // point index
    int sub = gtid & 3;         // segment index within point
    int ptc = min(pt, N - 1);   // all lanes stay active (shuffle safety)
    bool valid = (pt < N);

    // ── table-independent preamble: overlaps the build kernel via PDL ──
    float px = fminf(fmaxf(__ldg(&points[2 * ptc]),     0.0f), WM1);
    float py = fminf(fmaxf(__ldg(&points[2 * ptc + 1]), 0.0f), WM1);
    float nx = __ldg(&normals[2 * ptc]);
    float ny = __ldg(&normals[2 * ptc + 1]);
    float dx = -ny, dy = nx;
    float inv = rsqrtf(dx * dx + dy * dy);
    dx *= inv; dy *= inv;

    float t_left  = (dx != 0.0f) ? (0.0f - px) / dx : -FLT_MAX;
    float t_right = (dx != 0.0f) ? (WM1  - px) / dx :  FLT_MAX;
    float t_top   = (dy != 0.0f) ? (0.0f - py) / dy : -FLT_MAX;
    float t_bot   = (dy != 0.0f) ? (WM1  - py) / dy :  FLT_MAX;
    float t_min = fmaxf(t_left,  t_top);
    float t_max = fminf(t_right, t_bot);

    float p1x = fmaf(t_min, dx, px), p1y = fmaf(t_min, dy, py);
    float p2x = fmaf(t_max, dx, px), p2y = fmaf(t_max, dy, py);
    // fold the 1/99 step into the direction once: coord(s) = fma(s, sv, p1)
    float svx = (p2x - p1x) * (1.0f / 99.0f);
    float svy = (p2y - p1y) * (1.0f / 99.0f);

    int s0 = sub * 25;          // this thread owns samples [s0, s0+24]
    float fs0 = (float)s0;      // exact (<= 75)

    // ── wait for build completion (first g_tab access is below) ──
    cudaGridDependencySynchronize();

    // clamped sample coords; fs is the sample index as an exact float.
    // Clamps are load-bearing (inverted t-intervals put raw coords far
    // outside the image for ~half the points).
    #define CL(v)   fminf(fmaxf((v), 0.0f), WM1)
    #define SXF(fs) CL(fmaf((fs), svx, p1x))
    #define SYF(fs) CL(fmaf((fs), svy, p1y))

    // ref sample: only sub 0
    float ref_val = 0.0f;
    if (sub == 0) {
        ushort4 qr = quad_at(px, py);
        ref_val = interp(qr, px, py);
    }

    // prologue: first group's 5 loads in flight
    ushort4 qA[G], qB[G];
    #pragma unroll
    for (int j = 0; j < G; j++)
        qA[j] = quad_at(SXF(fs0 + (float)j), SYF(fs0 + (float)j));

    float v_prev = 0.0f, v_cur = 0.0f, cx = 0.0f, cy = 0.0f;
    float v_first = 0.0f, v_second = 0.0f, cfx = 0.0f, cfy = 0.0f;

    float best_dist = FLT_MAX;   // squared distance (argmin-equivalent)
    int   best_idx  = (sub == 0) ? 0x7FFFFFFE : 0x7FFFFFFF;
    float best_val  = 0.0f;

    // 5 groups x 5 samples, double-buffered; coords recomputed bit-identically
    // at consume (same expression, same exact-int fs) -> no stored coords.
    float fg_pre = fs0 + 5.0f;   // float base of next group's samples
    float fg_con = fs0;          // float base of current group's samples
    for (int g = 0; g < 5; g++) {               // rolled (R8/R12 lesson)
        if (g < 4) {
            #pragma unroll
            for (int j = 0; j < G; j++)
                qB[j] = quad_at(SXF(fg_pre + (float)j), SYF(fg_pre + (float)j));
        }
        int kbase = g * G;
        #pragma unroll
        for (int j = 0; j < G; j++) {
            int k = kbase + j;                   // local sample index 0..24
            float ax = SXF(fg_con + (float)j);
            float ay = SYF(fg_con + (float)j);
            float vn = interp(qA[j], ax, ay);
            if (k == 0) {
                v_first = vn; cfx = ax; cfy = ay;
                v_cur = vn;
            } else {
                if (k == 1) v_second = vn;
                if (k >= 2 && v_cur < v_prev && v_cur < vn) {
                    // interior window center k-1 (global s0+k-1); coords (cx,cy)
                    float ddx = cx - px, ddy = cy - py;
                    float d2 = fmaf(ddx, ddx, ddy * ddy);
                    if (d2 < best_dist) {        // ascending + strict < = first min
                        best_dist = d2;
                        best_idx  = s0 + k - 1;
                        best_val  = v_cur;
                    }
                }
                v_prev = v_cur;
                v_cur  = vn;
            }
            cx = ax; cy = ay;
        }
        #pragma unroll
        for (int j = 0; j < G; j++)
            qA[j] = qB[j];
        fg_pre += 5.0f;          // exact small-int floats
        fg_con += 5.0f;
    }
    #undef CL
    #undef SXF
    #undef SYF

    // boundary values from neighbor subs (same warp, adjacent lanes)
    float nb_last  = __shfl_up_sync(0xFFFFFFFFu, v_cur, 1);    // prev sub's v[24]
    float nb_first = __shfl_down_sync(0xFFFFFFFFu, v_first, 1);// next sub's v[0]

    // left-boundary window: center s0 (sub>0): (nb_last, v_first, v_second)
    if (sub > 0 && v_first < nb_last && v_first < v_second) {
        float ddx = cfx - px, ddy = cfy - py;
        float d2 = fmaf(ddx, ddx, ddy * ddy);
        if (d2 < best_dist || (d2 == best_dist && s0 < best_idx)) {
            best_dist = d2; best_idx = s0; best_val = v_first;
        }
    }
    // right-boundary window: center s0+24 (sub<3): (v_prev, v_cur, nb_first)
    if (sub < 3 && v_cur < v_prev && v_cur < nb_first) {
        float ddx = cx - px, ddy = cy - py;
        float d2 = fmaf(ddx, ddx, ddy * ddy);
        if (d2 < best_dist || (d2 == best_dist && (s0 + 24) < best_idx)) {
            best_dist = d2; best_idx = s0 + 24; best_val = v_cur;
        }
    }
    // all-inf default: argmin -> 0 -> vals[1] = global sample 1 = sub0's v_second
    if (sub == 0 && best_idx == 0x7FFFFFFE) best_val = v_second;

    // combine across the 4 sub-threads (lexicographic on (dist2, idx))
    #pragma unroll
    for (int m = 1; m <= 2; m <<= 1) {
        float od = __shfl_xor_sync(0xFFFFFFFFu, best_dist, m);
        int   oi = __shfl_xor_sync(0xFFFFFFFFu, best_idx,  m);
        float ov = __shfl_xor_sync(0xFFFFFFFFu, best_val,  m);
        if (od < best_dist || (od == best_dist && oi < best_idx)) {
            best_dist = od; best_idx = oi; best_val = ov;
        }
    }

    float sq = 0.0f;
    if (valid && sub == 0) {
        float diff = (best_val - ref_val) * QINV;   // scale once
        sq = diff * diff;
    }

    // ── block reduction (deterministic) ──
    __shared__ float smem[TPB / 32];
    __shared__ bool s_last;
    float v = sq;
    #pragma unroll
    for (int off = 16; off > 0; off >>= 1)
        v += __shfl_down_sync(0xFFFFFFFFu, v, off);
    int lane = threadIdx.x & 31;
    int wid  = threadIdx.x >> 5;
    if (lane == 0) smem[wid] = v;
    __syncthreads();
    if (wid == 0) {
        v = (lane < TPB / 32) ? smem[lane] : 0.0f;
        #pragma unroll
        for (int off = 2; off > 0; off >>= 1)
            v += __shfl_down_sync(0xFFFFFFFFu, v, off);
        if (lane == 0) {
            g_partials[blockIdx.x] = v;
            __threadfence();
            unsigned int t = atomicInc(&g_count, (unsigned int)(nblocks - 1));
            s_last = (t == (unsigned int)(nblocks - 1));
        }
    }
    __syncthreads();

    if (s_last) {
        float acc = 0.0f;
        for (int k = threadIdx.x; k < nblocks; k += TPB)
            acc += g_partials[k];
        #pragma unroll
        for (int off = 16; off > 0; off >>= 1)
            acc += __shfl_down_sync(0xFFFFFFFFu, acc, off);
        if (lane == 0) smem[wid] = acc;
        __syncthreads();
        if (wid == 0) {
            acc = (lane < TPB / 32) ? smem[lane] : 0.0f;
            #pragma unroll
            for (int off = 2; off > 0; off >>= 1)
                acc += __shfl_down_sync(0xFFFFFFFFu, acc, off);
            if (lane == 0) out[0] = acc * inv_n;
        }
    }
}

extern "C" void kernel_launch(void* const* d_in, const int* in_sizes, int n_in,
                              void* d_out, int out_size) {
    const float* img     = (const float*)d_in[0];
    const float* points  = (const float*)d_in[1];
    const float* normals = (const float*)d_in[2];
    float* out = (float*)d_out;

    int N = in_sizes[1] / 2;
    int total = N * SPLIT;
    int blocks = (total + TPB - 1) / TPB;

    // primary: build (1 thread per 2 cols x 4 rows)
    build_tab_kernel<<<((IMG_H / ROWS_PT) * (IMG_W / 2)) / BUILD_TPB, BUILD_TPB>>>(img);

    // secondary: PDL launch — preamble overlaps the build kernel
    cudaLaunchConfig_t cfg = {};
    cfg.gridDim  = dim3((unsigned)blocks, 1, 1);
    cfg.blockDim = dim3(TPB, 1, 1);
    cudaLaunchAttribute attrs[1];
    attrs[0].id = cudaLaunchAttributeProgrammaticStreamSerialization;
    attrs[0].val.programmaticStreamSerializationAllowed = 1;
    cfg.attrs = attrs;
    cfg.numAttrs = 1;
    float inv_n = 1.0f / (float)N;
    cudaLaunchKernelEx(&cfg, contour_loss_kernel, points, normals, out,
                       N, blocks, inv_n);
}